// round 10
// baseline (speedup 1.0000x reference)
#include <cuda_runtime.h>
#include <cuda_bf16.h>
#include <math.h>
#include <stdint.h>

#define N    8192
#define D    256
#define INV_T (1.0f / 0.7f)
#define EX2SC (1.44269504088896f * INV_T)   // log2(e)/T

#define TM 128
#define TN 128
#define GI (N / TM)                  // 64
#define NTILES (GI * (GI + 1) / 2)   // 2080
#define NCTA 148

// ---------------- device scratch ----------------
__device__ __nv_bfloat16 g_Pb[N * D];
__device__ float g_A[N];
__device__ float g_B[N];
__device__ float g_selfsim[N];
__device__ int   g_cls[N];
__device__ int   g_bar;              // phase-0 grid barrier (self-resetting)
__device__ int   g_done;             // finalize election (self-resetting)

// ---------------- helpers ----------------
__device__ __forceinline__ uint32_t smem_u32(const void* p) {
    uint32_t a;
    asm("{ .reg .u64 t; cvta.to.shared.u64 t, %1; cvt.u32.u64 %0, t; }"
        : "=r"(a) : "l"(p));
    return a;
}
#define SW128(off) ((off) ^ (((off) >> 3) & 0x70))

__device__ __forceinline__ void cp16(uint32_t dst, const void* src) {
    asm volatile("cp.async.cg.shared.global [%0], [%1], 16;" :: "r"(dst), "l"(src));
}
__device__ __forceinline__ void cp_commit() {
    asm volatile("cp.async.commit_group;" ::: "memory");
}
__device__ __forceinline__ void ldsm4(uint32_t& r0, uint32_t& r1,
                                      uint32_t& r2, uint32_t& r3, uint32_t addr) {
    asm volatile("ldmatrix.sync.aligned.m8n8.x4.shared.b16 {%0,%1,%2,%3}, [%4];"
                 : "=r"(r0), "=r"(r1), "=r"(r2), "=r"(r3) : "r"(addr));
}
__device__ __forceinline__ void mma16816(float* d, const uint32_t* a,
                                         const uint32_t* b) {
    asm volatile("mma.sync.aligned.m16n8k16.row.col.f32.bf16.bf16.f32 "
                 "{%0,%1,%2,%3}, {%4,%5,%6,%7}, {%8,%9}, {%0,%1,%2,%3};"
                 : "+f"(d[0]), "+f"(d[1]), "+f"(d[2]), "+f"(d[3])
                 : "r"(a[0]), "r"(a[1]), "r"(a[2]), "r"(a[3]),
                   "r"(b[0]), "r"(b[1]));
}
__device__ __forceinline__ float ex2(float x) {
    float r;
    asm("ex2.approx.f32 %0, %1;" : "=f"(r) : "f"(x));
    return r;
}

// ---------------- SMEM layout: all 4 bf16 chunks resident ----------------
#define ACH(c) ((c) * 16384)
#define BCH(c) (65536 + (c) * 16384)
#define CLSI_OFF  131072
#define CLSJ_OFF  131584
#define SACCI_OFF 132096
#define SBCCI_OFF 132608
#define SACCJ_OFF 133120
#define SBCCJ_OFF 133632
#define SMEM_BYTES 134144

// ---------------------------------------------------------------------------
__device__ __forceinline__ void map_tile(int t, int& bi, int& bj) {
    int b = 0, r = t;
    #pragma unroll 1
    while (r >= GI - b) { r -= GI - b; b++; }
    bi = b; bj = b + r;
}

__device__ __forceinline__ void issue_chunk(uint32_t sbase, int ck,
                                            int iBase, int jBase, int tid) {
    #pragma unroll
    for (int q = 0; q < 4; q++) {
        int s  = tid + q * 256;
        int r  = s >> 3;
        int sg = s & 7;
        uint32_t soff = SW128((uint32_t)(r * 128 + sg * 16));
        cp16(sbase + ACH(ck) + soff, g_Pb + (size_t)(iBase + r) * D + ck * 64 + sg * 8);
        cp16(sbase + BCH(ck) + soff, g_Pb + (size_t)(jBase + r) * D + ck * 64 + sg * 8);
    }
    cp_commit();
}

__device__ __forceinline__ void load_frags(uint32_t aB, uint32_t bB, int ks,
                                           int m0, int n0, int lrow, int lkoff,
                                           uint32_t afr[4][4], uint32_t bfr[4][2]) {
    #pragma unroll
    for (int nf2 = 0; nf2 < 2; nf2++) {
        uint32_t r0, r1, r2, r3;
        uint32_t off = (uint32_t)((n0 + nf2 * 16 + lrow) * 128 + lkoff + ks * 32);
        ldsm4(r0, r1, r2, r3, bB + SW128(off));
        bfr[nf2 * 2 + 0][0] = r0; bfr[nf2 * 2 + 0][1] = r2;
        bfr[nf2 * 2 + 1][0] = r1; bfr[nf2 * 2 + 1][1] = r3;
    }
    #pragma unroll
    for (int mf = 0; mf < 4; mf++) {
        uint32_t off = (uint32_t)((m0 + mf * 16 + lrow) * 128 + lkoff + ks * 32);
        ldsm4(afr[mf][0], afr[mf][1], afr[mf][2], afr[mf][3], aB + SW128(off));
    }
}

__device__ __forceinline__ void compute_chunk(uint32_t sbase, int ck,
                                              int m0, int n0, int lrow, int lkoff,
                                              uint32_t afr[2][4][4],
                                              uint32_t bfr[2][4][2],
                                              float acc[4][4][4]) {
    const uint32_t aB = sbase + ACH(ck);
    const uint32_t bB = sbase + BCH(ck);
    load_frags(aB, bB, 0, m0, n0, lrow, lkoff, afr[0], bfr[0]);
    #pragma unroll
    for (int ks = 0; ks < 4; ks++) {
        const int cur = ks & 1;
        if (ks < 3)
            load_frags(aB, bB, ks + 1, m0, n0, lrow, lkoff, afr[cur ^ 1], bfr[cur ^ 1]);
        #pragma unroll
        for (int mf = 0; mf < 4; mf++)
            #pragma unroll
            for (int nf = 0; nf < 4; nf++)
                mma16816(acc[mf][nf], afr[cur][mf], bfr[cur][nf]);
    }
}

// ---------------------------------------------------------------------------
// k_all: phase0 normalize + grid barrier + phase1 tiles + phase2 finalize
// ---------------------------------------------------------------------------
__global__ void __launch_bounds__(256, 1) k_all(const float* __restrict__ P,
                                                const void* __restrict__ yv,
                                                float* __restrict__ out) {
    extern __shared__ __align__(128) unsigned char smem[];
    const uint32_t sbase = smem_u32(smem);
    const int tid  = threadIdx.x;
    const int wid  = tid >> 5;
    const int lane = tid & 31;
    const int bid  = blockIdx.x;
    const int nCta = gridDim.x;

    int*   clsI  = (int*)(smem + CLSI_OFF);
    int*   clsJ  = (int*)(smem + CLSJ_OFF);
    float* sAccI = (float*)(smem + SACCI_OFF);
    float* sBccI = (float*)(smem + SBCCI_OFF);
    float* sAccJ = (float*)(smem + SACCJ_OFF);
    float* sBccJ = (float*)(smem + SBCCJ_OFF);

    // ===================== phase 0: normalize =====================
    __shared__ int s_is64;
    __shared__ int s_rank;
    if (wid == 0) {   // detect: int64 y<10 => all odd 32-bit words zero
        int v = ((const int*)yv)[2 * lane + 1];
        unsigned any = __ballot_sync(0xffffffffu, v != 0);
        if (lane == 0) s_is64 = (any == 0) ? 1 : 0;
    }
    if (bid < 32) {
        int idx = bid * 256 + tid;
        g_A[idx] = 0.0f; g_B[idx] = 0.0f;
    }
    __syncthreads();
    const int is64 = s_is64;

    const int nWarps = nCta * 8;
    #pragma unroll 1
    for (int row = bid * 8 + wid; row < N; row += nWarps) {
        const float4* p4 = (const float4*)(P + (size_t)row * D);
        float4 v0 = p4[lane];
        float4 v1 = p4[lane + 32];

        float ss = v0.x*v0.x + v0.y*v0.y + v0.z*v0.z + v0.w*v0.w
                 + v1.x*v1.x + v1.y*v1.y + v1.z*v1.z + v1.w*v1.w;
        #pragma unroll
        for (int o = 16; o; o >>= 1) ss += __shfl_xor_sync(0xffffffffu, ss, o);
        float rn = rsqrtf(ss);

        __nv_bfloat16 h[8];
        h[0] = __float2bfloat16(v0.x * rn); h[1] = __float2bfloat16(v0.y * rn);
        h[2] = __float2bfloat16(v0.z * rn); h[3] = __float2bfloat16(v0.w * rn);
        h[4] = __float2bfloat16(v1.x * rn); h[5] = __float2bfloat16(v1.y * rn);
        h[6] = __float2bfloat16(v1.z * rn); h[7] = __float2bfloat16(v1.w * rn);

        float sb = 0.0f;
        #pragma unroll
        for (int q = 0; q < 8; q++) { float f = __bfloat162float(h[q]); sb += f * f; }
        #pragma unroll
        for (int o = 16; o; o >>= 1) sb += __shfl_xor_sync(0xffffffffu, sb, o);

        *(uint2*)(g_Pb + (size_t)row * D + lane * 4)       = *(uint2*)&h[0];
        *(uint2*)(g_Pb + (size_t)row * D + 128 + lane * 4) = *(uint2*)&h[4];

        if (lane == 0) {
            int c = is64 ? (int)((const long long*)yv)[row] : ((const int*)yv)[row];
            g_cls[row]     = c;
            g_selfsim[row] = sb;
        }
    }

    // grid barrier
    __threadfence();
    __syncthreads();
    if (tid == 0) {
        atomicAdd(&g_bar, 1);
        while (*(volatile int*)&g_bar < nCta) { }
    }
    __syncthreads();

    // ===================== phase 1: tiles (R9 pipeline) =====================
    int tile = bid;
    if (tile < NTILES) {
        int biBlk, bjBlk;
        map_tile(tile, biBlk, bjBlk);
        int iBase = biBlk * TM;
        int jBase = bjBlk * TN;
        bool offdiag = (biBlk != bjBlk);

        if (tid < 128) {
            clsI[tid] = g_cls[iBase + tid];
            sAccI[tid] = 0.0f; sBccI[tid] = 0.0f;
            sAccJ[tid] = 0.0f; sBccJ[tid] = 0.0f;
        } else {
            clsJ[tid - 128] = g_cls[jBase + tid - 128];
        }
        #pragma unroll
        for (int ck = 0; ck < 4; ck++) issue_chunk(sbase, ck, iBase, jBase, tid);

        const int m0 = (wid >> 2) * 64;
        const int n0 = (wid & 3) * 32;
        const int lrow  = lane & 15;
        const int lkoff = (lane >> 4) * 16;
        const int gl   = lane >> 2;
        const int quad = lane & 3;

        #pragma unroll 1
        while (true) {
            int ntile = tile + nCta;
            const bool last = (ntile >= NTILES);
            int nbi, nbj;
            if (last) { nbi = biBlk; nbj = bjBlk; }
            else      map_tile(ntile, nbi, nbj);
            const int niBase = nbi * TM;
            const int njBase = nbj * TN;

            float acc[4][4][4];
            #pragma unroll
            for (int mf = 0; mf < 4; mf++)
                #pragma unroll
                for (int nf = 0; nf < 4; nf++)
                    #pragma unroll
                    for (int e = 0; e < 4; e++) acc[mf][nf][e] = 0.0f;

            uint32_t afr[2][4][4], bfr[2][4][2];

            asm volatile("cp.async.wait_group 3;" ::: "memory");
            __syncthreads();
            compute_chunk(sbase, 0, m0, n0, lrow, lkoff, afr, bfr, acc);
            asm volatile("cp.async.wait_group 2;" ::: "memory");
            __syncthreads();
            issue_chunk(sbase, 0, niBase, njBase, tid);
            compute_chunk(sbase, 1, m0, n0, lrow, lkoff, afr, bfr, acc);
            asm volatile("cp.async.wait_group 2;" ::: "memory");
            __syncthreads();
            issue_chunk(sbase, 1, niBase, njBase, tid);
            compute_chunk(sbase, 2, m0, n0, lrow, lkoff, afr, bfr, acc);
            asm volatile("cp.async.wait_group 2;" ::: "memory");
            __syncthreads();
            issue_chunk(sbase, 2, niBase, njBase, tid);
            compute_chunk(sbase, 3, m0, n0, lrow, lkoff, afr, bfr, acc);

            // ---- epilogue ----
            int cjr[8];
            #pragma unroll
            for (int q = 0; q < 8; q++)
                cjr[q] = clsJ[n0 + (q >> 1) * 8 + quad * 2 + (q & 1)];

            float aCol[8], bCol[8];
            #pragma unroll
            for (int q = 0; q < 8; q++) { aCol[q] = 0.0f; bCol[q] = 0.0f; }

            #pragma unroll
            for (int rr = 0; rr < 2; rr++) {
                #pragma unroll
                for (int mf = 0; mf < 4; mf++) {
                    const int rl = m0 + mf * 16 + gl + rr * 8;
                    const int ci = clsI[rl];
                    float aRow = 0.0f, bRow = 0.0f;
                    #pragma unroll
                    for (int q = 0; q < 8; q++) {
                        const float s = acc[mf][q >> 1][rr * 2 + (q & 1)];
                        const bool same = (ci == cjr[q]);
                        const float v = ex2(s * (same ? -EX2SC : EX2SC));
                        const float va = same ? 0.0f : v;
                        const float vb = v - va;
                        aRow += va; bRow += vb;
                        aCol[q] += va; bCol[q] += vb;
                    }
                    aRow += __shfl_xor_sync(0xffffffffu, aRow, 1);
                    aRow += __shfl_xor_sync(0xffffffffu, aRow, 2);
                    bRow += __shfl_xor_sync(0xffffffffu, bRow, 1);
                    bRow += __shfl_xor_sync(0xffffffffu, bRow, 2);
                    if (quad == 0) {
                        atomicAdd(&sAccI[rl], aRow);
                        atomicAdd(&sBccI[rl], bRow);
                    }
                }
            }

            if (offdiag) {
                #pragma unroll
                for (int q = 0; q < 8; q++) {
                    float a = aCol[q], b = bCol[q];
                    #pragma unroll
                    for (int o = 4; o <= 16; o <<= 1) {
                        a += __shfl_xor_sync(0xffffffffu, a, o);
                        b += __shfl_xor_sync(0xffffffffu, b, o);
                    }
                    if (lane < 4) {
                        const int cl = n0 + (q >> 1) * 8 + quad * 2 + (q & 1);
                        atomicAdd(&sAccJ[cl], a);
                        atomicAdd(&sBccJ[cl], b);
                    }
                }
            }

            __syncthreads();
            issue_chunk(sbase, 3, niBase, njBase, tid);

            if (tid < 128) {
                atomicAdd(&g_A[iBase + tid], sAccI[tid]);
                atomicAdd(&g_B[iBase + tid], sBccI[tid]);
                if (offdiag) {
                    atomicAdd(&g_A[jBase + tid], sAccJ[tid]);
                    atomicAdd(&g_B[jBase + tid], sBccJ[tid]);
                }
                sAccI[tid] = 0.0f; sBccI[tid] = 0.0f;
                sAccJ[tid] = 0.0f; sBccJ[tid] = 0.0f;
                clsI[tid] = g_cls[niBase + tid];
            } else {
                clsJ[tid - 128] = g_cls[njBase + tid - 128];
            }

            if (last) break;
            tile = ntile; biBlk = nbi; bjBlk = nbj;
            iBase = niBase; jBase = njBase;
            offdiag = (nbi != nbj);
        }
    }

    // ===================== phase 2: last-CTA finalize =====================
    __threadfence();
    __syncthreads();
    if (tid == 0) s_rank = atomicAdd(&g_done, 1);
    __syncthreads();
    if (s_rank == nCta - 1) {
        __threadfence();
        float* red  = sAccI;
        int*   hist = clsI;
        if (tid < 16) hist[tid] = 0;
        __syncthreads();
        for (int r = tid; r < N; r += 256) atomicAdd(&hist[g_cls[r] & 15], 1);
        __syncthreads();

        const float MF = __expf(0.5f * INV_T);
        float sum = 0.0f;
        for (int r = tid; r < N; r += 256) {
            int   c   = g_cls[r] & 15;
            int   cnt = hist[c];
            float Bv  = __ldcg(&g_B[r]) - __expf(-g_selfsim[r] * INV_T);
            float Av  = (N - cnt > 0) ? __ldcg(&g_A[r]) : 1.0f;
            Bv        = (cnt - 1 > 0) ? Bv : 1.0f;
            sum += log1pf(MF * Av * Bv);
        }
        red[tid] = sum;
        __syncthreads();
        #pragma unroll
        for (int s = 128; s; s >>= 1) {
            if (tid < s) red[tid] += red[tid + s];
            __syncthreads();
        }
        if (tid == 0) {
            out[0] = red[0] / (float)N;
            g_done = 0;                      // reset for next graph replay
            g_bar  = 0;
        }
    }
}

// ---------------------------------------------------------------------------
extern "C" void kernel_launch(void* const* d_in, const int* in_sizes, int n_in,
                              void* d_out, int out_size) {
    const float* P = (const float*)d_in[0];
    const void*  y = d_in[1];
    float*     out = (float*)d_out;

    cudaFuncSetAttribute(k_all, cudaFuncAttributeMaxDynamicSharedMemorySize,
                         SMEM_BYTES);

    int sms = NCTA;
    cudaDeviceGetAttribute(&sms, cudaDevAttrMultiProcessorCount, 0);
    int grid = sms < NTILES ? sms : NTILES;

    k_all<<<grid, 256, SMEM_BYTES>>>(P, y, out);
}

// round 11
// speedup vs baseline: 1.0778x; 1.0778x over previous
#include <cuda_runtime.h>
#include <cuda_fp16.h>
#include <math.h>
#include <stdint.h>

#define N    8192
#define D    256
#define INV_T (1.0f / 0.7f)
#define EX2SC (1.44269504088896f * INV_T)   // log2(e)/T

#define TM 128
#define TN 128
#define GI (N / TM)                  // 64
#define NTILES (GI * (GI + 1) / 2)   // 2080

// ---------------- device scratch ----------------
__device__ __half g_Ph[N * D];       // normalized rows, f16, row-major
__device__ float g_A[N];
__device__ float g_B[N];
__device__ float g_selfsim[N];
__device__ int   g_cls[N];

// ---------------- helpers ----------------
__device__ __forceinline__ uint32_t smem_u32(const void* p) {
    uint32_t a;
    asm("{ .reg .u64 t; cvta.to.shared.u64 t, %1; cvt.u32.u64 %0, t; }"
        : "=r"(a) : "l"(p));
    return a;
}
#define SW128(off) ((off) ^ (((off) >> 3) & 0x70))

__device__ __forceinline__ void cp16(uint32_t dst, const void* src) {
    asm volatile("cp.async.cg.shared.global [%0], [%1], 16;" :: "r"(dst), "l"(src));
}
__device__ __forceinline__ void cp_commit() {
    asm volatile("cp.async.commit_group;" ::: "memory");
}
__device__ __forceinline__ void ldsm4(uint32_t& r0, uint32_t& r1,
                                      uint32_t& r2, uint32_t& r3, uint32_t addr) {
    asm volatile("ldmatrix.sync.aligned.m8n8.x4.shared.b16 {%0,%1,%2,%3}, [%4];"
                 : "=r"(r0), "=r"(r1), "=r"(r2), "=r"(r3) : "r"(addr));
}
// f16 x f16 -> f16 accumulate (2 regs = 4 halves, same element mapping as f32 d0..d3)
__device__ __forceinline__ void mma16816h(uint32_t* d, const uint32_t* a,
                                          const uint32_t* b) {
    asm volatile("mma.sync.aligned.m16n8k16.row.col.f16.f16.f16.f16 "
                 "{%0,%1}, {%2,%3,%4,%5}, {%6,%7}, {%0,%1};"
                 : "+r"(d[0]), "+r"(d[1])
                 : "r"(a[0]), "r"(a[1]), "r"(a[2]), "r"(a[3]),
                   "r"(b[0]), "r"(b[1]));
}
__device__ __forceinline__ float ex2(float x) {
    float r;
    asm("ex2.approx.f32 %0, %1;" : "=f"(r) : "f"(x));
    return r;
}

// ---------------- SMEM layout: all 4 f16 chunks resident ----------------
#define ACH(c) ((c) * 16384)             // 128 rows x 128 B (SW128)
#define BCH(c) (65536 + (c) * 16384)
#define CLSI_OFF  131072
#define CLSJ_OFF  131584
#define SACCI_OFF 132096
#define SBCCI_OFF 132608
#define SACCJ_OFF 133120
#define SBCCJ_OFF 133632
#define SMEM_BYTES 134144

// ---------------------------------------------------------------------------
// k_norm: dtype detect + zero A/B + normalize->f16 + selfsim + class
// ---------------------------------------------------------------------------
__global__ void k_norm(const float* __restrict__ P, const void* __restrict__ yv) {
    __shared__ int s_is64;
    const int tid  = threadIdx.x;
    const int w    = tid >> 5;
    const int lane = tid & 31;
    const int row  = blockIdx.x * 8 + w;

    if (w == 0) {   // detect: int64 y<10 => all odd 32-bit words zero
        int v = ((const int*)yv)[2 * lane + 1];
        unsigned any = __ballot_sync(0xffffffffu, v != 0);
        if (lane == 0) s_is64 = (any == 0) ? 1 : 0;
    }
    if (blockIdx.x < 32) {              // zero accumulators
        int idx = blockIdx.x * 256 + tid;
        g_A[idx] = 0.0f; g_B[idx] = 0.0f;
    }
    __syncthreads();
    const int is64 = s_is64;

    const float4* p4 = (const float4*)(P + (size_t)row * D);
    float4 v0 = p4[lane];
    float4 v1 = p4[lane + 32];

    float ss = v0.x*v0.x + v0.y*v0.y + v0.z*v0.z + v0.w*v0.w
             + v1.x*v1.x + v1.y*v1.y + v1.z*v1.z + v1.w*v1.w;
    #pragma unroll
    for (int o = 16; o; o >>= 1) ss += __shfl_xor_sync(0xffffffffu, ss, o);
    float rn = rsqrtf(ss);

    __half h[8];
    h[0] = __float2half_rn(v0.x * rn); h[1] = __float2half_rn(v0.y * rn);
    h[2] = __float2half_rn(v0.z * rn); h[3] = __float2half_rn(v0.w * rn);
    h[4] = __float2half_rn(v1.x * rn); h[5] = __float2half_rn(v1.y * rn);
    h[6] = __float2half_rn(v1.z * rn); h[7] = __float2half_rn(v1.w * rn);

    float sb = 0.0f;
    #pragma unroll
    for (int q = 0; q < 8; q++) { float f = __half2float(h[q]); sb += f * f; }
    #pragma unroll
    for (int o = 16; o; o >>= 1) sb += __shfl_xor_sync(0xffffffffu, sb, o);

    *(uint2*)(g_Ph + (size_t)row * D + lane * 4)       = *(uint2*)&h[0];
    *(uint2*)(g_Ph + (size_t)row * D + 128 + lane * 4) = *(uint2*)&h[4];

    if (lane == 0) {
        int c = is64 ? (int)((const long long*)yv)[row] : ((const int*)yv)[row];
        g_cls[row]     = c;
        g_selfsim[row] = sb;
    }
}

// ---------------------------------------------------------------------------
__device__ __forceinline__ void map_tile(int t, int& bi, int& bj) {
    int b = 0, r = t;
    #pragma unroll 1
    while (r >= GI - b) { r -= GI - b; b++; }
    bi = b; bj = b + r;
}

__device__ __forceinline__ void issue_chunk(uint32_t sbase, int ck,
                                            int iBase, int jBase, int tid) {
    #pragma unroll
    for (int q = 0; q < 4; q++) {
        int s  = tid + q * 256;
        int r  = s >> 3;
        int sg = s & 7;
        uint32_t soff = SW128((uint32_t)(r * 128 + sg * 16));
        cp16(sbase + ACH(ck) + soff, g_Ph + (size_t)(iBase + r) * D + ck * 64 + sg * 8);
        cp16(sbase + BCH(ck) + soff, g_Ph + (size_t)(jBase + r) * D + ck * 64 + sg * 8);
    }
    cp_commit();
}

__device__ __forceinline__ void load_frags(uint32_t aB, uint32_t bB, int ks,
                                           int m0, int n0, int lrow, int lkoff,
                                           uint32_t afr[4][4], uint32_t bfr[4][2]) {
    #pragma unroll
    for (int nf2 = 0; nf2 < 2; nf2++) {
        uint32_t r0, r1, r2, r3;
        uint32_t off = (uint32_t)((n0 + nf2 * 16 + lrow) * 128 + lkoff + ks * 32);
        ldsm4(r0, r1, r2, r3, bB + SW128(off));
        bfr[nf2 * 2 + 0][0] = r0; bfr[nf2 * 2 + 0][1] = r2;
        bfr[nf2 * 2 + 1][0] = r1; bfr[nf2 * 2 + 1][1] = r3;
    }
    #pragma unroll
    for (int mf = 0; mf < 4; mf++) {
        uint32_t off = (uint32_t)((m0 + mf * 16 + lrow) * 128 + lkoff + ks * 32);
        ldsm4(afr[mf][0], afr[mf][1], afr[mf][2], afr[mf][3], aB + SW128(off));
    }
}

__device__ __forceinline__ void compute_chunk(uint32_t sbase, int ck,
                                              int m0, int n0, int lrow, int lkoff,
                                              uint32_t afr[2][4][4],
                                              uint32_t bfr[2][4][2],
                                              uint32_t acc[4][4][2]) {
    const uint32_t aB = sbase + ACH(ck);
    const uint32_t bB = sbase + BCH(ck);
    load_frags(aB, bB, 0, m0, n0, lrow, lkoff, afr[0], bfr[0]);
    #pragma unroll
    for (int ks = 0; ks < 4; ks++) {
        const int cur = ks & 1;
        if (ks < 3)
            load_frags(aB, bB, ks + 1, m0, n0, lrow, lkoff, afr[cur ^ 1], bfr[cur ^ 1]);
        #pragma unroll
        for (int mf = 0; mf < 4; mf++)
            #pragma unroll
            for (int nf = 0; nf < 4; nf++)
                mma16816h(acc[mf][nf], afr[cur][mf], bfr[cur][nf]);
    }
}

// ---------------------------------------------------------------------------
// k_main: persistent CTAs, upper-triangle tiles, cross-tile cp.async pipeline,
// f16-accumulate MMA.
// ---------------------------------------------------------------------------
__global__ void __launch_bounds__(256, 1) k_main() {
    extern __shared__ __align__(128) unsigned char smem[];
    const uint32_t sbase = smem_u32(smem);
    const int tid  = threadIdx.x;
    const int wid  = tid >> 5;
    const int lane = tid & 31;

    int*   clsI  = (int*)(smem + CLSI_OFF);
    int*   clsJ  = (int*)(smem + CLSJ_OFF);
    float* sAccI = (float*)(smem + SACCI_OFF);
    float* sBccI = (float*)(smem + SBCCI_OFF);
    float* sAccJ = (float*)(smem + SACCJ_OFF);
    float* sBccJ = (float*)(smem + SBCCJ_OFF);

    int tile = blockIdx.x;
    if (tile >= NTILES) return;

    int biBlk, bjBlk;
    map_tile(tile, biBlk, bjBlk);
    int iBase = biBlk * TM;
    int jBase = bjBlk * TN;
    bool offdiag = (biBlk != bjBlk);

    if (tid < 128) {
        clsI[tid] = g_cls[iBase + tid];
        sAccI[tid] = 0.0f; sBccI[tid] = 0.0f;
        sAccJ[tid] = 0.0f; sBccJ[tid] = 0.0f;
    } else {
        clsJ[tid - 128] = g_cls[jBase + tid - 128];
    }
    #pragma unroll
    for (int ck = 0; ck < 4; ck++) issue_chunk(sbase, ck, iBase, jBase, tid);

    const int m0 = (wid >> 2) * 64;
    const int n0 = (wid & 3) * 32;
    const int lrow  = lane & 15;
    const int lkoff = (lane >> 4) * 16;
    const int gl   = lane >> 2;
    const int quad = lane & 3;

    #pragma unroll 1
    while (true) {
        int ntile = tile + gridDim.x;
        const bool last = (ntile >= NTILES);
        int nbi, nbj;
        if (last) { nbi = biBlk; nbj = bjBlk; }
        else      map_tile(ntile, nbi, nbj);
        const int niBase = nbi * TM;
        const int njBase = nbj * TN;

        uint32_t acc[4][4][2];
        #pragma unroll
        for (int mf = 0; mf < 4; mf++)
            #pragma unroll
            for (int nf = 0; nf < 4; nf++) { acc[mf][nf][0] = 0u; acc[mf][nf][1] = 0u; }

        uint32_t afr[2][4][4], bfr[2][4][2];

        asm volatile("cp.async.wait_group 3;" ::: "memory");
        __syncthreads();
        compute_chunk(sbase, 0, m0, n0, lrow, lkoff, afr, bfr, acc);
        asm volatile("cp.async.wait_group 2;" ::: "memory");
        __syncthreads();
        issue_chunk(sbase, 0, niBase, njBase, tid);
        compute_chunk(sbase, 1, m0, n0, lrow, lkoff, afr, bfr, acc);
        asm volatile("cp.async.wait_group 2;" ::: "memory");
        __syncthreads();
        issue_chunk(sbase, 1, niBase, njBase, tid);
        compute_chunk(sbase, 2, m0, n0, lrow, lkoff, afr, bfr, acc);
        asm volatile("cp.async.wait_group 2;" ::: "memory");
        __syncthreads();
        issue_chunk(sbase, 2, niBase, njBase, tid);
        compute_chunk(sbase, 3, m0, n0, lrow, lkoff, afr, bfr, acc);

        // ---- epilogue: unpack f16 acc -> float, masked exp sums ----
        int cjr[8];
        #pragma unroll
        for (int q = 0; q < 8; q++)
            cjr[q] = clsJ[n0 + (q >> 1) * 8 + quad * 2 + (q & 1)];

        float aCol[8], bCol[8];
        #pragma unroll
        for (int q = 0; q < 8; q++) { aCol[q] = 0.0f; bCol[q] = 0.0f; }

        #pragma unroll
        for (int rr = 0; rr < 2; rr++) {
            #pragma unroll
            for (int mf = 0; mf < 4; mf++) {
                const int rl = m0 + mf * 16 + gl + rr * 8;
                const int ci = clsI[rl];
                float aRow = 0.0f, bRow = 0.0f;
                #pragma unroll
                for (int q = 0; q < 8; q++) {
                    const int nf = q >> 1;
                    float2 pr = __half22float2(
                        *(const __half2*)&acc[mf][nf][rr]);  // reg rr = {d(2rr), d(2rr+1)}
                    const float s = (q & 1) ? pr.y : pr.x;
                    const bool same = (ci == cjr[q]);
                    const float v = ex2(s * (same ? -EX2SC : EX2SC));
                    const float va = same ? 0.0f : v;
                    const float vb = v - va;
                    aRow += va; bRow += vb;
                    aCol[q] += va; bCol[q] += vb;
                }
                aRow += __shfl_xor_sync(0xffffffffu, aRow, 1);
                aRow += __shfl_xor_sync(0xffffffffu, aRow, 2);
                bRow += __shfl_xor_sync(0xffffffffu, bRow, 1);
                bRow += __shfl_xor_sync(0xffffffffu, bRow, 2);
                if (quad == 0) {
                    atomicAdd(&sAccI[rl], aRow);
                    atomicAdd(&sBccI[rl], bRow);
                }
            }
        }

        if (offdiag) {
            #pragma unroll
            for (int q = 0; q < 8; q++) {
                float a = aCol[q], b = bCol[q];
                #pragma unroll
                for (int o = 4; o <= 16; o <<= 1) {
                    a += __shfl_xor_sync(0xffffffffu, a, o);
                    b += __shfl_xor_sync(0xffffffffu, b, o);
                }
                if (lane < 4) {
                    const int cl = n0 + (q >> 1) * 8 + quad * 2 + (q & 1);
                    atomicAdd(&sAccJ[cl], a);
                    atomicAdd(&sBccJ[cl], b);
                }
            }
        }

        __syncthreads();
        issue_chunk(sbase, 3, niBase, njBase, tid);

        if (tid < 128) {
            atomicAdd(&g_A[iBase + tid], sAccI[tid]);
            atomicAdd(&g_B[iBase + tid], sBccI[tid]);
            if (offdiag) {
                atomicAdd(&g_A[jBase + tid], sAccJ[tid]);
                atomicAdd(&g_B[jBase + tid], sBccJ[tid]);
            }
            sAccI[tid] = 0.0f; sBccI[tid] = 0.0f;
            sAccJ[tid] = 0.0f; sBccJ[tid] = 0.0f;
            clsI[tid] = g_cls[niBase + tid];
        } else {
            clsJ[tid - 128] = g_cls[njBase + tid - 128];
        }

        if (last) break;
        tile = ntile; biBlk = nbi; bjBlk = nbj;
        iBase = niBase; jBase = njBase;
        offdiag = (nbi != nbj);
    }
}

// ---------------------------------------------------------------------------
// k_loss: histogram locally, subtract self term, empty-set semantics, mean
// ---------------------------------------------------------------------------
__global__ void k_loss(float* __restrict__ out) {
    __shared__ float red[256];
    __shared__ int hist[16];
    const int tid = threadIdx.x;
    if (tid < 16) hist[tid] = 0;
    __syncthreads();
    for (int r = tid; r < N; r += 256) atomicAdd(&hist[g_cls[r] & 15], 1);
    __syncthreads();

    const float MF = __expf(0.5f * INV_T);
    float sum = 0.0f;
    for (int r = tid; r < N; r += 256) {
        int   c   = g_cls[r] & 15;
        int   cnt = hist[c];
        // self term as the f16 MMA computed it: round selfsim to f16
        float ssh = __half2float(__float2half_rn(g_selfsim[r]));
        float Bv  = g_B[r] - __expf(-ssh * INV_T);
        float Av  = (N - cnt > 0) ? g_A[r] : 1.0f;
        Bv        = (cnt - 1 > 0) ? Bv : 1.0f;
        sum += log1pf(MF * Av * Bv);
    }
    red[tid] = sum;
    __syncthreads();
    #pragma unroll
    for (int s = 128; s; s >>= 1) {
        if (tid < s) red[tid] += red[tid + s];
        __syncthreads();
    }
    if (tid == 0) out[0] = red[0] / (float)N;
}

// ---------------------------------------------------------------------------
extern "C" void kernel_launch(void* const* d_in, const int* in_sizes, int n_in,
                              void* d_out, int out_size) {
    const float* P = (const float*)d_in[0];
    const void*  y = d_in[1];
    float*     out = (float*)d_out;

    cudaFuncSetAttribute(k_main, cudaFuncAttributeMaxDynamicSharedMemorySize,
                         SMEM_BYTES);

    int sms = 148;
    cudaDeviceGetAttribute(&sms, cudaDevAttrMultiProcessorCount, 0);
    int grid = sms < NTILES ? sms : NTILES;

    k_norm<<<N / 8, 256>>>(P, y);
    k_main<<<grid, 256, SMEM_BYTES>>>();
    k_loss<<<1, 256>>>(out);
}